// round 16
// baseline (speedup 1.0000x reference)
#include <cuda_runtime.h>
#include <cuda_fp16.h>
#include <cstdint>

// ---------------- problem constants ----------------
#define NTOT   8192
#define BHALF  4096
#define DD     256
#define TILE   128
#define KC     64       // K-chunk halves = 128 B/row (swizzle atom)
#define NCHUNK 4        // 256 / 64
#define NT     256      // 8 warps, 2x4 warp grid
#define NTILES 64
#define NBLK   (NTILES * (NTILES + 1) / 2)   // 2080 tile blocks
#define NCONV  256                           // convert blocks (32 rows each)
#define GRID   (NCONV + NBLK)

// smem: [A0 16K][B0 16K][A1 16K][B1 16K][sq 1K][red 32B]
#define STAGE_BYTES 32768u
#define B_OFF       16384u
#define SQ_OFF      65536u
#define RED_OFF     66560u
#define SMEM_TOTAL  66624

// ---------------- device scratch ----------------
__device__ __half   g_x[NTOT * DD];
__device__ float    g_sq[NTOT];
__device__ float    g_sqpart[NCONV];
__device__ float    g_colpart[32 * DD];  // 32 slices; zero-init; reset by bw block
__device__ float    g_m;
__device__ double   g_acc;
__device__ unsigned g_tdone[NTILES];     // per-tile convert counters (==4 -> ready)
__device__ unsigned g_mflag;             // g_m published
__device__ unsigned g_cnt1;              // convert completion counter
__device__ unsigned g_cnt2;              // tile completion counter

// ---------------- helpers ----------------
__device__ __forceinline__ uint32_t smem_u32(const void* p) {
    uint32_t a;
    asm("{ .reg .u64 t; cvta.to.shared.u64 t, %1; cvt.u32.u64 %0, t; }"
        : "=r"(a) : "l"(p));
    return a;
}
__device__ __forceinline__ void ldsm_x4(uint32_t& r0, uint32_t& r1,
                                        uint32_t& r2, uint32_t& r3,
                                        uint32_t addr) {
    asm volatile("ldmatrix.sync.aligned.m8n8.x4.shared.b16 {%0,%1,%2,%3}, [%4];"
                 : "=r"(r0), "=r"(r1), "=r"(r2), "=r"(r3) : "r"(addr));
}
__device__ __forceinline__ void mma_f16acc(uint32_t* d, const uint32_t* a,
                                           uint32_t b0, uint32_t b1) {
    asm volatile(
        "mma.sync.aligned.m16n8k16.row.col.f16.f16.f16.f16 "
        "{%0,%1}, {%2,%3,%4,%5}, {%6,%7}, {%0,%1};"
        : "+r"(d[0]), "+r"(d[1])
        : "r"(a[0]), "r"(a[1]), "r"(a[2]), "r"(a[3]), "r"(b0), "r"(b1));
}

// ---------------- chunk loader: 2048 x 16B, 8 per thread ----------------
__device__ __forceinline__ void load_chunk(uint32_t sb, int buf,
                                           const __half* gA, const __half* gB,
                                           int k0, int tid) {
    uint32_t aB = sb + buf * STAGE_BYTES;
    uint32_t bB = aB + B_OFF;
    #pragma unroll
    for (int i = 0; i < 4; i++) {
        int u = tid + i * 256;
        int row = u >> 3, c = u & 7;
        uint32_t off = (uint32_t)(row * 128 + c * 16);
        uint32_t sw = off ^ ((off >> 3) & 0x70);
        const __half* srcA = gA + (size_t)row * DD + k0 + c * 8;
        const __half* srcB = gB + (size_t)row * DD + k0 + c * 8;
        asm volatile("cp.async.cg.shared.global [%0], [%1], 16;"
                     :: "r"(aB + sw), "l"(srcA));
        asm volatile("cp.async.cg.shared.global [%0], [%1], 16;"
                     :: "r"(bB + sw), "l"(srcB));
    }
    asm volatile("cp.async.commit_group;" ::: "memory");
}

// ---------------- fused kernel: convert blocks + tile blocks ----------------
__global__ void __launch_bounds__(NT, 3) mmd_fused_kernel(
        const float* __restrict__ xs, const float* __restrict__ xt,
        float* __restrict__ out) {
    extern __shared__ char smem[];
    int bid = blockIdx.x;
    int tid = threadIdx.x, wid = tid >> 5, lane = tid & 31;

    if (bid < NCONV) {
        // ======== convert block: rows [bid*32, bid*32+32) ========
        float* scol2 = (float*)smem;              // 8*256 floats
        float* ws    = (float*)(smem + SQ_OFF);   // 8 floats
        int c0 = lane * 8;
        float colacc[8] = {0.f,0.f,0.f,0.f,0.f,0.f,0.f,0.f};
        float wsum = 0.f;                         // lane 0
        #pragma unroll
        for (int r = 0; r < 4; r++) {
            int row = bid * 32 + wid * 4 + r;
            const float* p = (row < BHALF) ? xs + (size_t)row * DD
                                           : xt + (size_t)(row - BHALF) * DD;
            float4 v0 = *(const float4*)(p + c0);
            float4 v1 = *(const float4*)(p + c0 + 4);
            float f[8] = {v0.x, v0.y, v0.z, v0.w, v1.x, v1.y, v1.z, v1.w};
            float s = 0.f;
            half2 h2[4];
            #pragma unroll
            for (int j = 0; j < 4; j++) {
                __half h0 = __float2half_rn(f[2 * j]);
                __half h1 = __float2half_rn(f[2 * j + 1]);
                h2[j] = __halves2half2(h0, h1);
                float t0 = __half2float(h0), t1 = __half2float(h1);
                s = fmaf(t0, t0, s); s = fmaf(t1, t1, s);
                colacc[2 * j]     += t0;
                colacc[2 * j + 1] += t1;
            }
            *(int4*)(g_x + (size_t)row * DD + c0) = *(int4*)h2;
            #pragma unroll
            for (int o = 16; o; o >>= 1) s += __shfl_xor_sync(0xffffffffu, s, o);
            if (lane == 0) { g_sq[row] = s; wsum += s; }
        }
        #pragma unroll
        for (int j = 0; j < 8; j++) scol2[wid * DD + c0 + j] = colacc[j];
        if (lane == 0) ws[wid] = wsum;
        __syncthreads();

        {
            float cp = 0.f;
            #pragma unroll
            for (int w = 0; w < 8; w++) cp += scol2[w * DD + tid];
            atomicAdd(&g_colpart[(bid & 31) * DD + tid], cp);
        }
        if (tid == 0) {
            float b = 0.f;
            #pragma unroll
            for (int w = 0; w < 8; w++) b += ws[w];
            g_sqpart[bid] = b;
        }

        // publish: this block's rows + partials are globally visible
        __threadfence();
        __syncthreads();
        if (tid == 0) atomicAdd(&g_tdone[bid >> 2], 1u);   // tile = bid/4

        // last convert block computes bandwidth and publishes g_m
        __shared__ int s_last;
        if (tid == 0) s_last = (atomicAdd(&g_cnt1, 1u) == (unsigned)NCONV - 1u);
        __syncthreads();
        if (!s_last) return;

        float cs = 0.f;
        #pragma unroll 4
        for (int b2 = 0; b2 < 32; b2++) cs += g_colpart[b2 * DD + tid];
        float sq = g_sqpart[tid];

        __shared__ double sh[256];
        sh[tid] = (double)cs * (double)cs;
        __syncthreads();
        for (int s2 = 128; s2; s2 >>= 1) { if (tid < s2) sh[tid] += sh[tid + s2]; __syncthreads(); }
        double cs_tot = sh[0];
        __syncthreads();
        sh[tid] = (double)sq;
        __syncthreads();
        for (int s2 = 128; s2; s2 >>= 1) { if (tid < s2) sh[tid] += sh[tid + s2]; __syncthreads(); }
        #pragma unroll 4
        for (int b2 = 0; b2 < 32; b2++) g_colpart[b2 * DD + tid] = 0.f;  // reset
        if (tid == 0) {
            double sumsq = sh[0];
            double n = (double)NTOT;
            double sumL2 = 2.0 * n * sumsq - 2.0 * cs_tot;
            double bw = sumL2 / (n * n - n) / 4.0;
            g_m = (float)(1.4426950408889634 / (bw * 16.0));
            g_acc = 0.0;
            g_cnt1 = 0u;
            __threadfence();
            atomicExch(&g_mflag, 1u);
        }
        return;
    }

    // ======== tile block (EXACT round-13 mainloop) ========
    int b = bid - NCONV;
    int ti = (int)((sqrtf(8.f * (float)b + 1.f) - 1.f) * 0.5f);
    while ((ti + 1) * (ti + 2) / 2 <= b) ti++;
    while (ti * (ti + 1) / 2 > b) ti--;
    int tj = b - ti * (ti + 1) / 2;

    // wait for both tiles' rows to be converted (convert blocks are all in
    // wave 1, so this spin resolves quickly and only for early tile blocks)
    if (tid == 0) {
        while (*(volatile unsigned*)&g_tdone[ti] < 4u ||
               *(volatile unsigned*)&g_tdone[tj] < 4u)
            __nanosleep(64);
    }
    __syncthreads();
    __threadfence();

    uint32_t sb = smem_u32(smem);
    const __half* gA = g_x + (size_t)ti * TILE * DD;
    const __half* gB = g_x + (size_t)tj * TILE * DD;

    load_chunk(sb, 0, gA, gB, 0, tid);

    float* sqrow = (float*)(smem + SQ_OFF);
    float* sqcol = sqrow + TILE;
    if (tid < TILE) sqrow[tid] = g_sq[ti * TILE + tid];
    else            sqcol[tid - TILE] = g_sq[tj * TILE + (tid - TILE)];

    int wm = (wid >> 2) * 64;
    int wn = (wid & 3) * 32;

    uint32_t acc[4][4][2];
    #pragma unroll
    for (int a = 0; a < 4; a++)
        #pragma unroll
        for (int c = 0; c < 4; c++) { acc[a][c][0] = 0u; acc[a][c][1] = 0u; }

    int grp = lane >> 3, rin = lane & 7;
    int aRow = wm + (grp & 1) * 8 + rin;
    int aKB  = (grp >> 1) * 16;
    int bRow = wn + (grp >> 1) * 8 + rin;
    int bKB  = (grp & 1) * 16;
    uint32_t aMask = (uint32_t)((aRow & 7) << 4);
    uint32_t bMask = (uint32_t)((bRow & 7) << 4);

    for (int ck = 0; ck < NCHUNK; ck++) {
        if (ck < NCHUNK - 1) {
            load_chunk(sb, (ck + 1) & 1, gA, gB, (ck + 1) * KC, tid);
            asm volatile("cp.async.wait_group 1;" ::: "memory");
        } else {
            asm volatile("cp.async.wait_group 0;" ::: "memory");
        }
        __syncthreads();

        uint32_t aB = sb + (uint32_t)(ck & 1) * STAGE_BYTES;
        uint32_t bB = aB + B_OFF;

        #pragma unroll
        for (int ks = 0; ks < 4; ks++) {
            uint32_t a[4][4], bf[2][4];
            #pragma unroll
            for (int mt = 0; mt < 4; mt++) {
                uint32_t addr = aB + (uint32_t)((aRow + mt * 16) * 128)
                              + (((uint32_t)(ks * 32 + aKB)) ^ aMask);
                ldsm_x4(a[mt][0], a[mt][1], a[mt][2], a[mt][3], addr);
            }
            #pragma unroll
            for (int nh = 0; nh < 2; nh++) {
                uint32_t addr = bB + (uint32_t)((bRow + nh * 16) * 128)
                              + (((uint32_t)(ks * 32 + bKB)) ^ bMask);
                ldsm_x4(bf[nh][0], bf[nh][1], bf[nh][2], bf[nh][3], addr);
            }
            #pragma unroll
            for (int mt = 0; mt < 4; mt++)
                #pragma unroll
                for (int nt = 0; nt < 4; nt++)
                    mma_f16acc(acc[mt][nt], a[mt],
                               bf[nt >> 1][(nt & 1) * 2],
                               bf[nt >> 1][(nt & 1) * 2 + 1]);
        }
        __syncthreads();
    }

    // acquire g_m (published ~3us in; epilogues start >30us in)
    __shared__ float s_m;
    if (tid == 0) {
        while (*(volatile unsigned*)&g_mflag == 0u) __nanosleep(64);
        __threadfence();
        s_m = *(volatile float*)&g_m;
    }
    __syncthreads();
    float m = s_m;

    // ---- epilogue: L2 -> 5-kernel RBF sum ----
    int rbase = wm + (lane >> 2);
    int cbase = wn + ((lane & 3) << 1);
    int rglob = ti * TILE, cglob = tj * TILE;
    float total = 0.f;
    #pragma unroll
    for (int mt = 0; mt < 4; mt++) {
        int rr = rbase + mt * 16;
        #pragma unroll
        for (int nt = 0; nt < 4; nt++) {
            int cc = cbase + nt * 8;
            float sb0 = sqcol[cc], sb1 = sqcol[cc + 1];
            #pragma unroll
            for (int e2 = 0; e2 < 2; e2++) {
                int rl = rr + e2 * 8;
                float sa = sqrow[rl];
                float2 dv = __half22float2(*(const half2*)&acc[mt][nt][e2]);
                float L2a = fmaxf(sa + sb0 - 2.f * dv.x, 0.f);
                float L2b = fmaxf(sa + sb1 - 2.f * dv.y, 0.f);
                float ea, eb;
                asm("ex2.approx.ftz.f32 %0, %1;" : "=f"(ea) : "f"(-L2a * m));
                asm("ex2.approx.ftz.f32 %0, %1;" : "=f"(eb) : "f"(-L2b * m));
                float ea1 = ea * ea, ea2 = ea1 * ea1, ea3 = ea2 * ea2, ea4 = ea3 * ea3;
                float eb1 = eb * eb, eb2 = eb1 * eb1, eb3 = eb2 * eb2, eb4 = eb3 * eb3;
                float kva = ((ea + ea1) + (ea2 + ea3)) + ea4;
                float kvb = ((eb + eb1) + (eb2 + eb3)) + eb4;
                int rg = rglob + rl, cg = cglob + cc;
                total += (rg > cg)     ? kva : 0.f;
                total += (rg > cg + 1) ? kvb : 0.f;
            }
        }
    }
    total *= (((ti < 32) == (tj < 32)) ? 2.f : -2.f);

    #pragma unroll
    for (int o = 16; o; o >>= 1) total += __shfl_xor_sync(0xffffffffu, total, o);
    float* red = (float*)(smem + RED_OFF);
    if (lane == 0) red[wid] = total;
    __syncthreads();
    __shared__ int s_fin;
    if (tid == 0) {
        float s = 0.f;
        #pragma unroll
        for (int w = 0; w < 8; w++) s += red[w];
        atomicAdd(&g_acc, (double)s);
        __threadfence();
        s_fin = (atomicAdd(&g_cnt2, 1u) == (unsigned)NBLK - 1u);
    }
    __syncthreads();
    if (s_fin) {
        // all tile blocks have passed their spins (they did so before g_cnt2++)
        if (tid < NTILES) g_tdone[tid] = 0u;
        if (tid == 0) {
            out[0] = (float)((g_acc + (double)NTOT * 5.0) /
                             ((double)BHALF * (double)BHALF));
            g_cnt2 = 0u;
            g_mflag = 0u;
        }
    }
}

// ---------------- launch ----------------
extern "C" void kernel_launch(void* const* d_in, const int* in_sizes, int n_in,
                              void* d_out, int out_size) {
    const float* xs = (const float*)d_in[0];
    const float* xt = (const float*)d_in[1];
    float* out = (float*)d_out;

    cudaFuncSetAttribute(mmd_fused_kernel,
                         cudaFuncAttributeMaxDynamicSharedMemorySize, SMEM_TOTAL);

    mmd_fused_kernel<<<GRID, NT, SMEM_TOTAL>>>(xs, xt, out);
}